// round 6
// baseline (speedup 1.0000x reference)
#include <cuda_runtime.h>
#include <cuda_bf16.h>
#include <math.h>
#include <stdint.h>

#define NN 4096
#define IN_DIM 256
#define HIDDEN 512
#define CLASSES 256
#define HEADS 4
#define HD 64
#define EE 131072

// ---------------- scratch ----------------
#define OFF_DINV 0L
#define OFF_H1   (OFF_DINV + NN)
#define OFF_AGG1 (OFF_H1   + (long)NN * HIDDEN)
#define OFF_H2   (OFF_AGG1 + (long)NN * HIDDEN)
#define OFF_AGG2 (OFF_H2   + (long)NN * HIDDEN)
#define OFF_GNN  (OFF_AGG2 + (long)NN * HIDDEN)
#define OFF_ATTN (OFF_GNN  + (long)NN * CLASSES)
#define OFF_XTF  (OFF_ATTN + (long)NN * IN_DIM)
#define SCRATCH_TOTAL (OFF_XTF + (long)NN * IN_DIM)

__device__ __align__(16) float g_scratch[SCRATCH_TOTAL];
__device__ __align__(16) __nv_bfloat16 g_qkvh[(long)NN * 3 * IN_DIM];

// ---------------- degree / norm ----------------
__global__ void deg_init_kernel() {
    int i = blockIdx.x * blockDim.x + threadIdx.x;
    if (i < NN) g_scratch[OFF_DINV + i] = 1.0f;
}
__global__ void deg_count_kernel(const int* __restrict__ ei) {
    int i = blockIdx.x * blockDim.x + threadIdx.x;
    if (i < EE) atomicAdd(&g_scratch[OFF_DINV + ei[EE + i]], 1.0f);
}
__global__ void deg_finalize_kernel() {
    int i = blockIdx.x * blockDim.x + threadIdx.x;
    if (i < NN) g_scratch[OFF_DINV + i] = rsqrtf(g_scratch[OFF_DINV + i]);
}

// ---------------- tf32 helpers ----------------
__device__ __forceinline__ float to_tf32(float x) {
    float r;
    asm("cvt.rna.tf32.f32 %0, %1;" : "=f"(r) : "f"(x));
    return r;
}
__device__ __forceinline__ void mma_tf32(float c[4], float a0, float a1, float a2,
                                         float a3, float b0, float b1) {
    uint32_t ua0 = __float_as_uint(a0), ua1 = __float_as_uint(a1);
    uint32_t ua2 = __float_as_uint(a2), ua3 = __float_as_uint(a3);
    uint32_t ub0 = __float_as_uint(b0), ub1 = __float_as_uint(b1);
    asm volatile(
        "mma.sync.aligned.m16n8k8.row.col.f32.tf32.tf32.f32 "
        "{%0,%1,%2,%3},{%4,%5,%6,%7},{%8,%9},{%0,%1,%2,%3};\n"
        : "+f"(c[0]), "+f"(c[1]), "+f"(c[2]), "+f"(c[3])
        : "r"(ua0), "r"(ua1), "r"(ua2), "r"(ua3), "r"(ub0), "r"(ub1));
}

// ---------------- tf32 tensor-core GEMM ----------------
// C[M,Nd] = A[M,K] @ (TRANSB ? B[Nd,K]^T : B[K,Nd]) (+bias)(+add)(relu)
// BM=128, BN=64, BK=16, 256 threads (8 warps), warp w -> rows [w*16,w*16+16)
#define AP 20
#define BP 72
template <bool TRANSB, bool RELU, bool HASBIAS, bool HASADD, bool OUTBF16>
__global__ __launch_bounds__(256) void gemm_tc(const float* __restrict__ Aext, long aoff,
                                               const float* __restrict__ B,
                                               const float* __restrict__ bias,
                                               long addoff,
                                               float* __restrict__ Cext, long coff,
                                               int M, int K, int Nd) {
    const float* __restrict__ A = Aext ? Aext : (const float*)(g_scratch + aoff);
    float* __restrict__ C = Cext ? Cext : (g_scratch + coff);
    const float* __restrict__ addsrc = g_scratch + (HASADD ? addoff : 0);

    __shared__ float As[128][AP];
    __shared__ float Bs[16][BP];

    const int tid = threadIdx.x;
    const int warp = tid >> 5, lane = tid & 31;
    const int fr = lane >> 2, fc = lane & 3;  // fragment row/col
    const int mw = warp * 16;
    const int m0 = blockIdx.y * 128, n0 = blockIdx.x * 64;

    float acc[8][4];
#pragma unroll
    for (int nt = 0; nt < 8; nt++)
#pragma unroll
        for (int j = 0; j < 4; j++) acc[nt][j] = 0.0f;

    for (int k0 = 0; k0 < K; k0 += 16) {
        // stage A tile [128][16]
#pragma unroll
        for (int u = 0; u < 2; u++) {
            int idx = u * 256 + tid;
            int m = idx >> 2;
            int kq = (idx & 3) * 4;
            float4 v = *(const float4*)(A + (size_t)(m0 + m) * K + k0 + kq);
            As[m][kq + 0] = to_tf32(v.x);
            As[m][kq + 1] = to_tf32(v.y);
            As[m][kq + 2] = to_tf32(v.z);
            As[m][kq + 3] = to_tf32(v.w);
        }
        // stage B tile [16][64]
        if (TRANSB) {
            int n = tid >> 2;
            int kq = (tid & 3) * 4;
            float4 v = *(const float4*)(B + (size_t)(n0 + n) * K + k0 + kq);
            Bs[kq + 0][n] = to_tf32(v.x);
            Bs[kq + 1][n] = to_tf32(v.y);
            Bs[kq + 2][n] = to_tf32(v.z);
            Bs[kq + 3][n] = to_tf32(v.w);
        } else {
            int kr = tid >> 4;
            int n4 = (tid & 15) * 4;
            float4 v = *(const float4*)(B + (size_t)(k0 + kr) * Nd + n0 + n4);
            Bs[kr][n4 + 0] = to_tf32(v.x);
            Bs[kr][n4 + 1] = to_tf32(v.y);
            Bs[kr][n4 + 2] = to_tf32(v.z);
            Bs[kr][n4 + 3] = to_tf32(v.w);
        }
        __syncthreads();

#pragma unroll
        for (int ks = 0; ks < 2; ks++) {
            int kk = ks * 8;
            float a0 = As[mw + fr][kk + fc];
            float a1 = As[mw + fr + 8][kk + fc];
            float a2 = As[mw + fr][kk + fc + 4];
            float a3 = As[mw + fr + 8][kk + fc + 4];
#pragma unroll
            for (int nt = 0; nt < 8; nt++) {
                float b0 = Bs[kk + fc][nt * 8 + fr];
                float b1 = Bs[kk + fc + 4][nt * 8 + fr];
                mma_tf32(acc[nt], a0, a1, a2, a3, b0, b1);
            }
        }
        __syncthreads();
    }

    // epilogue
    int r0 = m0 + mw + fr;
    int r1 = r0 + 8;
#pragma unroll
    for (int nt = 0; nt < 8; nt++) {
        int cc = n0 + nt * 8 + fc * 2;
        float v00 = acc[nt][0], v01 = acc[nt][1];
        float v10 = acc[nt][2], v11 = acc[nt][3];
        if (HASBIAS) {
            float b0 = bias[cc], b1 = bias[cc + 1];
            v00 += b0; v01 += b1; v10 += b0; v11 += b1;
        }
        if (HASADD) {
            float2 a0 = *(const float2*)&addsrc[(size_t)r0 * Nd + cc];
            float2 a1 = *(const float2*)&addsrc[(size_t)r1 * Nd + cc];
            v00 += a0.x; v01 += a0.y; v10 += a1.x; v11 += a1.y;
        }
        if (RELU) {
            v00 = fmaxf(v00, 0.0f); v01 = fmaxf(v01, 0.0f);
            v10 = fmaxf(v10, 0.0f); v11 = fmaxf(v11, 0.0f);
        }
        if (OUTBF16) {
            __nv_bfloat162 h0 = __floats2bfloat162_rn(v00, v01);
            __nv_bfloat162 h1 = __floats2bfloat162_rn(v10, v11);
            *(uint32_t*)&g_qkvh[(size_t)r0 * Nd + cc] = *(uint32_t*)&h0;
            *(uint32_t*)&g_qkvh[(size_t)r1 * Nd + cc] = *(uint32_t*)&h1;
        } else {
            *(float2*)&C[(size_t)r0 * Nd + cc] = make_float2(v00, v01);
            *(float2*)&C[(size_t)r1 * Nd + cc] = make_float2(v10, v11);
        }
    }
}

// ---------------- GCN aggregation ----------------
__global__ void selfloop_bias_kernel(long hoff, const float* __restrict__ b,
                                     long aggoff, int F) {
    const float* __restrict__ h = g_scratch + hoff;
    float* __restrict__ agg = g_scratch + aggoff;
    const float* __restrict__ dinv = g_scratch + OFF_DINV;
    int idx = blockIdx.x * blockDim.x + threadIdx.x;
    if (idx >= NN * F) return;
    int n = idx / F;
    int f = idx - n * F;
    float w = dinv[n] * dinv[n];
    agg[idx] = h[idx] * w + b[f];
}

__global__ void scatter_kernel(long hoff, const int* __restrict__ ei,
                               long aggoff, int F) {
    const float* __restrict__ h = g_scratch + hoff;
    float* __restrict__ agg = g_scratch + aggoff;
    const float* __restrict__ dinv = g_scratch + OFF_DINV;
    int idx = blockIdx.x * blockDim.x + threadIdx.x;
    int cpr = F >> 2;
    if (idx >= EE * cpr) return;
    int e = idx / cpr;
    int c = (idx - e * cpr) * 4;
    int src = ei[e];
    int dst = ei[EE + e];
    float w = dinv[src] * dinv[dst];
    float4 v = *(const float4*)(h + (size_t)src * F + c);
    float* p = agg + (size_t)dst * F + c;
    atomicAdd(p + 0, v.x * w);
    atomicAdd(p + 1, v.y * w);
    atomicAdd(p + 2, v.z * w);
    atomicAdd(p + 3, v.w * w);
}

__global__ void relu_kernel(long off, int n) {
    int i = blockIdx.x * blockDim.x + threadIdx.x;
    if (i < n) g_scratch[off + i] = fmaxf(g_scratch[off + i], 0.0f);
}

// ---------------- bf16 tensor-core flash attention ----------------
__device__ __forceinline__ void mma_bf16(float c[4], uint32_t a0, uint32_t a1,
                                         uint32_t a2, uint32_t a3,
                                         uint32_t b0, uint32_t b1) {
    asm volatile(
        "mma.sync.aligned.m16n8k16.row.col.f32.bf16.bf16.f32 "
        "{%0,%1,%2,%3},{%4,%5,%6,%7},{%8,%9},{%0,%1,%2,%3};\n"
        : "+f"(c[0]), "+f"(c[1]), "+f"(c[2]), "+f"(c[3])
        : "r"(a0), "r"(a1), "r"(a2), "r"(a3), "r"(b0), "r"(b1));
}

#define FA_PITCH 72

__global__ __launch_bounds__(128) void flash_attn_bf16_kernel() {
    const __nv_bfloat16* __restrict__ qkvh = g_qkvh;
    float* __restrict__ outp = g_scratch + OFF_ATTN;
    const int head = blockIdx.y;
    const int q0 = blockIdx.x * 64;
    const int tid = threadIdx.x;
    const int warp = tid >> 5;
    const int lane = tid & 31;
    const int quad = lane >> 2;
    const int qd = lane & 3;

    __shared__ __align__(16) __nv_bfloat16 Qs[64][FA_PITCH];
    __shared__ __align__(16) __nv_bfloat16 Ks[64][FA_PITCH];
    __shared__ __align__(16) __nv_bfloat16 Vt[64][FA_PITCH];
    __shared__ __align__(16) __nv_bfloat16 Ps[64][FA_PITCH];

#pragma unroll
    for (int ch = 0; ch < 4; ch++) {
        int idx = ch * 128 + tid;
        int r = idx >> 3;
        int c = (idx & 7) * 8;
        *(uint4*)&Qs[r][c] =
            *(const uint4*)&qkvh[(size_t)(q0 + r) * 768 + head * 64 + c];
    }

    float m0r = -1e30f, m1r = -1e30f;
    float l0r = 0.0f, l1r = 0.0f;
    float o[8][4];
#pragma unroll
    for (int nt = 0; nt < 8; nt++)
#pragma unroll
        for (int j = 0; j < 4; j++) o[nt][j] = 0.0f;

    const int qrowA = warp * 16 + quad;
    const int qrowB = qrowA + 8;

    for (int kb = 0; kb < NN / 64; kb++) {
        int kbase = kb * 64;
        __syncthreads();
#pragma unroll
        for (int ch = 0; ch < 4; ch++) {
            int idx = ch * 128 + tid;
            int r = idx >> 3;
            int c = (idx & 7) * 8;
            *(uint4*)&Ks[r][c] =
                *(const uint4*)&qkvh[(size_t)(kbase + r) * 768 + 256 + head * 64 + c];
        }
        {
            int r = tid & 63;
            int d0 = (tid >> 6) * 32;
#pragma unroll
            for (int u = 0; u < 4; u++) {
                uint4 vv = *(const uint4*)&qkvh[(size_t)(kbase + r) * 768 + 512 +
                                                head * 64 + d0 + u * 8];
                __nv_bfloat16 tmp[8];
                *(uint4*)tmp = vv;
#pragma unroll
                for (int j = 0; j < 8; j++) Vt[d0 + u * 8 + j][r] = tmp[j];
            }
        }
        __syncthreads();

        float sc[8][4];
#pragma unroll
        for (int nt = 0; nt < 8; nt++)
#pragma unroll
            for (int j = 0; j < 4; j++) sc[nt][j] = 0.0f;

#pragma unroll
        for (int ks = 0; ks < 4; ks++) {
            int k0 = ks * 16;
            uint32_t a0 = *(const uint32_t*)&Qs[qrowA][k0 + qd * 2];
            uint32_t a1 = *(const uint32_t*)&Qs[qrowB][k0 + qd * 2];
            uint32_t a2 = *(const uint32_t*)&Qs[qrowA][k0 + qd * 2 + 8];
            uint32_t a3 = *(const uint32_t*)&Qs[qrowB][k0 + qd * 2 + 8];
#pragma unroll
            for (int nt = 0; nt < 8; nt++) {
                uint32_t b0 = *(const uint32_t*)&Ks[nt * 8 + quad][k0 + qd * 2];
                uint32_t b1 = *(const uint32_t*)&Ks[nt * 8 + quad][k0 + qd * 2 + 8];
                mma_bf16(sc[nt], a0, a1, a2, a3, b0, b1);
            }
        }

        float mA = -1e30f, mB = -1e30f;
#pragma unroll
        for (int nt = 0; nt < 8; nt++) {
            sc[nt][0] *= 0.125f; sc[nt][1] *= 0.125f;
            sc[nt][2] *= 0.125f; sc[nt][3] *= 0.125f;
            mA = fmaxf(mA, fmaxf(sc[nt][0], sc[nt][1]));
            mB = fmaxf(mB, fmaxf(sc[nt][2], sc[nt][3]));
        }
        mA = fmaxf(mA, __shfl_xor_sync(0xffffffffu, mA, 1));
        mA = fmaxf(mA, __shfl_xor_sync(0xffffffffu, mA, 2));
        mB = fmaxf(mB, __shfl_xor_sync(0xffffffffu, mB, 1));
        mB = fmaxf(mB, __shfl_xor_sync(0xffffffffu, mB, 2));
        float mnA = fmaxf(m0r, mA);
        float mnB = fmaxf(m1r, mB);
        float alA = __expf(m0r - mnA);
        float alB = __expf(m1r - mnB);
        float sumA = 0.0f, sumB = 0.0f;
#pragma unroll
        for (int nt = 0; nt < 8; nt++) {
            float p0 = __expf(sc[nt][0] - mnA);
            float p1 = __expf(sc[nt][1] - mnA);
            float p2 = __expf(sc[nt][2] - mnB);
            float p3 = __expf(sc[nt][3] - mnB);
            sumA += p0 + p1;
            sumB += p2 + p3;
            __nv_bfloat162 hA = __floats2bfloat162_rn(p0, p1);
            __nv_bfloat162 hB = __floats2bfloat162_rn(p2, p3);
            *(uint32_t*)&Ps[qrowA][nt * 8 + qd * 2] = *(uint32_t*)&hA;
            *(uint32_t*)&Ps[qrowB][nt * 8 + qd * 2] = *(uint32_t*)&hB;
        }
        sumA += __shfl_xor_sync(0xffffffffu, sumA, 1);
        sumA += __shfl_xor_sync(0xffffffffu, sumA, 2);
        sumB += __shfl_xor_sync(0xffffffffu, sumB, 1);
        sumB += __shfl_xor_sync(0xffffffffu, sumB, 2);
        l0r = l0r * alA + sumA;
        l1r = l1r * alB + sumB;
        m0r = mnA;
        m1r = mnB;
#pragma unroll
        for (int nt = 0; nt < 8; nt++) {
            o[nt][0] *= alA; o[nt][1] *= alA;
            o[nt][2] *= alB; o[nt][3] *= alB;
        }
        __syncwarp();

#pragma unroll
        for (int ks = 0; ks < 4; ks++) {
            int k0 = ks * 16;
            uint32_t a0 = *(const uint32_t*)&Ps[qrowA][k0 + qd * 2];
            uint32_t a1 = *(const uint32_t*)&Ps[qrowB][k0 + qd * 2];
            uint32_t a2 = *(const uint32_t*)&Ps[qrowA][k0 + qd * 2 + 8];
            uint32_t a3 = *(const uint32_t*)&Ps[qrowB][k0 + qd * 2 + 8];
#pragma unroll
            for (int nt = 0; nt < 8; nt++) {
                uint32_t b0 = *(const uint32_t*)&Vt[nt * 8 + quad][k0 + qd * 2];
                uint32_t b1 = *(const uint32_t*)&Vt[nt * 8 + quad][k0 + qd * 2 + 8];
                mma_bf16(o[nt], a0, a1, a2, a3, b0, b1);
            }
        }
    }

    float invA = 1.0f / l0r;
    float invB = 1.0f / l1r;
    int gA = q0 + qrowA;
    int gB = q0 + qrowB;
#pragma unroll
    for (int nt = 0; nt < 8; nt++) {
        float2 vA = make_float2(o[nt][0] * invA, o[nt][1] * invA);
        float2 vB = make_float2(o[nt][2] * invB, o[nt][3] * invB);
        *(float2*)&outp[(size_t)gA * IN_DIM + head * 64 + nt * 8 + qd * 2] = vA;
        *(float2*)&outp[(size_t)gB * IN_DIM + head * 64 + nt * 8 + qd * 2] = vB;
    }
}

// ---------------- launch ----------------
extern "C" void kernel_launch(void* const* d_in, const int* in_sizes, int n_in,
                              void* d_out, int out_size) {
    const float* x          = (const float*)d_in[0];
    const int*   ei         = (const int*)d_in[1];
    const float* gcn1_w     = (const float*)d_in[2];
    const float* gcn1_b     = (const float*)d_in[3];
    const float* gcn2_w     = (const float*)d_in[4];
    const float* gcn2_b     = (const float*)d_in[5];
    const float* lin_w      = (const float*)d_in[6];
    const float* lin_b      = (const float*)d_in[7];
    const float* in_proj_w  = (const float*)d_in[8];
    const float* in_proj_b  = (const float*)d_in[9];
    const float* out_proj_w = (const float*)d_in[10];
    const float* out_proj_b = (const float*)d_in[11];
    const float* proj_w     = (const float*)d_in[12];
    const float* proj_b     = (const float*)d_in[13];
    float* out = (float*)d_out;

    deg_init_kernel<<<NN / 256, 256>>>();
    deg_count_kernel<<<EE / 256, 256>>>(ei);
    deg_finalize_kernel<<<NN / 256, 256>>>();

    // ---- GNN branch ----
    gemm_tc<false, false, false, false, false><<<dim3(HIDDEN / 64, NN / 128), 256>>>(
        x, 0L, gcn1_w, nullptr, 0L, nullptr, OFF_H1, NN, IN_DIM, HIDDEN);
    selfloop_bias_kernel<<<(NN * HIDDEN) / 256, 256>>>(OFF_H1, gcn1_b, OFF_AGG1, HIDDEN);
    scatter_kernel<<<(EE * (HIDDEN / 4)) / 256, 256>>>(OFF_H1, ei, OFF_AGG1, HIDDEN);
    relu_kernel<<<(NN * HIDDEN) / 256, 256>>>(OFF_AGG1, NN * HIDDEN);

    gemm_tc<false, false, false, false, false><<<dim3(HIDDEN / 64, NN / 128), 256>>>(
        nullptr, OFF_AGG1, gcn2_w, nullptr, 0L, nullptr, OFF_H2, NN, HIDDEN, HIDDEN);
    selfloop_bias_kernel<<<(NN * HIDDEN) / 256, 256>>>(OFF_H2, gcn2_b, OFF_AGG2, HIDDEN);
    scatter_kernel<<<(EE * (HIDDEN / 4)) / 256, 256>>>(OFF_H2, ei, OFF_AGG2, HIDDEN);
    relu_kernel<<<(NN * HIDDEN) / 256, 256>>>(OFF_AGG2, NN * HIDDEN);

    gemm_tc<false, false, true, false, false><<<dim3(CLASSES / 64, NN / 128), 256>>>(
        nullptr, OFF_AGG2, lin_w, lin_b, 0L, nullptr, OFF_GNN, NN, HIDDEN, CLASSES);

    // ---- Transformer branch ----
    // qkv -> bf16 buffer directly
    gemm_tc<true, false, true, false, true><<<dim3((3 * IN_DIM) / 64, NN / 128), 256>>>(
        x, 0L, in_proj_w, in_proj_b, 0L, nullptr, 0L, NN, IN_DIM, 3 * IN_DIM);

    flash_attn_bf16_kernel<<<dim3(NN / 64, HEADS), 128>>>();

    gemm_tc<true, false, true, false, false><<<dim3(IN_DIM / 64, NN / 128), 256>>>(
        nullptr, OFF_ATTN, out_proj_w, out_proj_b, 0L, nullptr, OFF_XTF, NN, IN_DIM, IN_DIM);

    gemm_tc<false, true, true, true, false><<<dim3(CLASSES / 64, NN / 128), 256>>>(
        nullptr, OFF_XTF, proj_w, proj_b, OFF_GNN, out, 0L, NN, IN_DIM, CLASSES);
}

// round 7
// speedup vs baseline: 2.7075x; 2.7075x over previous
#include <cuda_runtime.h>
#include <cuda_bf16.h>
#include <math.h>
#include <stdint.h>

#define NN 4096
#define IN_DIM 256
#define HIDDEN 512
#define CLASSES 256
#define HEADS 4
#define HD 64
#define EE 131072

// ---------------- scratch ----------------
#define OFF_DINV 0L
#define OFF_H1   (OFF_DINV + NN)
#define OFF_AGG1 (OFF_H1   + (long)NN * HIDDEN)
#define OFF_H2   (OFF_AGG1 + (long)NN * HIDDEN)
#define OFF_AGG2 (OFF_H2   + (long)NN * HIDDEN)
#define OFF_GNN  (OFF_AGG2 + (long)NN * HIDDEN)
#define OFF_ATTN (OFF_GNN  + (long)NN * CLASSES)
#define OFF_XTF  (OFF_ATTN + (long)NN * IN_DIM)
#define SCRATCH_TOTAL (OFF_XTF + (long)NN * IN_DIM)

__device__ __align__(16) float g_scratch[SCRATCH_TOTAL];
__device__ __align__(16) __nv_bfloat16 g_qkvh[(long)NN * 3 * IN_DIM];
__device__ int g_cnt[NN];
__device__ int g_rowptr[NN + 1];
__device__ int g_srcidx[EE];

// ---------------- CSR build ----------------
__global__ void zero_cnt_kernel() {
    int i = blockIdx.x * blockDim.x + threadIdx.x;
    if (i < NN) g_cnt[i] = 0;
}
__global__ void hist_kernel(const int* __restrict__ ei) {
    int i = blockIdx.x * blockDim.x + threadIdx.x;
    if (i < EE) atomicAdd(&g_cnt[ei[EE + i]], 1);
}
// single block, 1024 threads: rowptr scan + dinv + reset cnt
__global__ __launch_bounds__(1024) void scan_kernel() {
    __shared__ int sh[1024];
    int t = threadIdx.x;
    int base = t * 4;
    int c0 = g_cnt[base + 0], c1 = g_cnt[base + 1];
    int c2 = g_cnt[base + 2], c3 = g_cnt[base + 3];
    int s = c0 + c1 + c2 + c3;
    sh[t] = s;
    __syncthreads();
    for (int off = 1; off < 1024; off <<= 1) {
        int v = (t >= off) ? sh[t - off] : 0;
        __syncthreads();
        sh[t] += v;
        __syncthreads();
    }
    int run = sh[t] - s;  // exclusive
    g_rowptr[base + 0] = run;            run += c0;
    g_rowptr[base + 1] = run;            run += c1;
    g_rowptr[base + 2] = run;            run += c2;
    g_rowptr[base + 3] = run;            run += c3;
    if (t == 1023) g_rowptr[NN] = run;
    g_scratch[OFF_DINV + base + 0] = rsqrtf((float)c0 + 1.0f);
    g_scratch[OFF_DINV + base + 1] = rsqrtf((float)c1 + 1.0f);
    g_scratch[OFF_DINV + base + 2] = rsqrtf((float)c2 + 1.0f);
    g_scratch[OFF_DINV + base + 3] = rsqrtf((float)c3 + 1.0f);
    g_cnt[base + 0] = 0; g_cnt[base + 1] = 0;
    g_cnt[base + 2] = 0; g_cnt[base + 3] = 0;
}
__global__ void fill_kernel(const int* __restrict__ ei) {
    int e = blockIdx.x * blockDim.x + threadIdx.x;
    if (e >= EE) return;
    int dst = ei[EE + e];
    int pos = g_rowptr[dst] + atomicAdd(&g_cnt[dst], 1);
    g_srcidx[pos] = ei[e];
}

// ---------------- fused GCN aggregation (gather, no atomics) ----------------
// agg[n, c0:c0+128] = relu( h[n]*dinv[n]^2 + bias + sum_{src in nbr(n)} h[src]*dinv[src]*dinv[n] )
// grid (NN/8, F/128), 256 threads (8 warps, one node per warp)
__global__ __launch_bounds__(256) void gather_kernel(long hoff, const float* __restrict__ bias,
                                                     long aggoff, int F) {
    const float* __restrict__ h = g_scratch + hoff;
    float* __restrict__ agg = g_scratch + aggoff;
    const float* __restrict__ dinv = g_scratch + OFF_DINV;
    const int warp = threadIdx.x >> 5;
    const int lane = threadIdx.x & 31;
    const int node = blockIdx.x * 8 + warp;
    const int c = blockIdx.y * 128 + lane * 4;

    float dd = dinv[node];
    float4 b4 = *(const float4*)&bias[c];
    float4 hv = *(const float4*)&h[(size_t)node * F + c];
    float sw = dd * dd;
    float4 acc = make_float4(hv.x * sw + b4.x, hv.y * sw + b4.y,
                             hv.z * sw + b4.z, hv.w * sw + b4.w);

    int beg = g_rowptr[node];
    int end = g_rowptr[node + 1];
    for (int j = beg; j < end; j++) {
        int src = g_srcidx[j];
        float w = dinv[src] * dd;
        float4 v = *(const float4*)&h[(size_t)src * F + c];
        acc.x += v.x * w; acc.y += v.y * w;
        acc.z += v.z * w; acc.w += v.w * w;
    }
    acc.x = fmaxf(acc.x, 0.0f); acc.y = fmaxf(acc.y, 0.0f);
    acc.z = fmaxf(acc.z, 0.0f); acc.w = fmaxf(acc.w, 0.0f);
    *(float4*)&agg[(size_t)node * F + c] = acc;
}

// ---------------- tf32 helpers ----------------
__device__ __forceinline__ float to_tf32(float x) {
    float r;
    asm("cvt.rna.tf32.f32 %0, %1;" : "=f"(r) : "f"(x));
    return r;
}
__device__ __forceinline__ void mma_tf32(float c[4], float a0, float a1, float a2,
                                         float a3, float b0, float b1) {
    uint32_t ua0 = __float_as_uint(a0), ua1 = __float_as_uint(a1);
    uint32_t ua2 = __float_as_uint(a2), ua3 = __float_as_uint(a3);
    uint32_t ub0 = __float_as_uint(b0), ub1 = __float_as_uint(b1);
    asm volatile(
        "mma.sync.aligned.m16n8k8.row.col.f32.tf32.tf32.f32 "
        "{%0,%1,%2,%3},{%4,%5,%6,%7},{%8,%9},{%0,%1,%2,%3};\n"
        : "+f"(c[0]), "+f"(c[1]), "+f"(c[2]), "+f"(c[3])
        : "r"(ua0), "r"(ua1), "r"(ua2), "r"(ua3), "r"(ub0), "r"(ub1));
}

// ---------------- tf32 tensor-core GEMM ----------------
#define AP 20
#define BP 72
template <bool TRANSB, bool RELU, bool HASBIAS, bool HASADD, bool OUTBF16>
__global__ __launch_bounds__(256) void gemm_tc(const float* __restrict__ Aext, long aoff,
                                               const float* __restrict__ B,
                                               const float* __restrict__ bias,
                                               long addoff,
                                               float* __restrict__ Cext, long coff,
                                               int M, int K, int Nd) {
    const float* __restrict__ A = Aext ? Aext : (const float*)(g_scratch + aoff);
    float* __restrict__ C = Cext ? Cext : (g_scratch + coff);
    const float* __restrict__ addsrc = g_scratch + (HASADD ? addoff : 0);

    __shared__ float As[128][AP];
    __shared__ float Bs[16][BP];

    const int tid = threadIdx.x;
    const int warp = tid >> 5, lane = tid & 31;
    const int fr = lane >> 2, fc = lane & 3;
    const int mw = warp * 16;
    const int m0 = blockIdx.y * 128, n0 = blockIdx.x * 64;

    float acc[8][4];
#pragma unroll
    for (int nt = 0; nt < 8; nt++)
#pragma unroll
        for (int j = 0; j < 4; j++) acc[nt][j] = 0.0f;

    for (int k0 = 0; k0 < K; k0 += 16) {
#pragma unroll
        for (int u = 0; u < 2; u++) {
            int idx = u * 256 + tid;
            int m = idx >> 2;
            int kq = (idx & 3) * 4;
            float4 v = *(const float4*)(A + (size_t)(m0 + m) * K + k0 + kq);
            As[m][kq + 0] = to_tf32(v.x);
            As[m][kq + 1] = to_tf32(v.y);
            As[m][kq + 2] = to_tf32(v.z);
            As[m][kq + 3] = to_tf32(v.w);
        }
        if (TRANSB) {
            int n = tid >> 2;
            int kq = (tid & 3) * 4;
            float4 v = *(const float4*)(B + (size_t)(n0 + n) * K + k0 + kq);
            Bs[kq + 0][n] = to_tf32(v.x);
            Bs[kq + 1][n] = to_tf32(v.y);
            Bs[kq + 2][n] = to_tf32(v.z);
            Bs[kq + 3][n] = to_tf32(v.w);
        } else {
            int kr = tid >> 4;
            int n4 = (tid & 15) * 4;
            float4 v = *(const float4*)(B + (size_t)(k0 + kr) * Nd + n0 + n4);
            Bs[kr][n4 + 0] = to_tf32(v.x);
            Bs[kr][n4 + 1] = to_tf32(v.y);
            Bs[kr][n4 + 2] = to_tf32(v.z);
            Bs[kr][n4 + 3] = to_tf32(v.w);
        }
        __syncthreads();

#pragma unroll
        for (int ks = 0; ks < 2; ks++) {
            int kk = ks * 8;
            float a0 = As[mw + fr][kk + fc];
            float a1 = As[mw + fr + 8][kk + fc];
            float a2 = As[mw + fr][kk + fc + 4];
            float a3 = As[mw + fr + 8][kk + fc + 4];
#pragma unroll
            for (int nt = 0; nt < 8; nt++) {
                float b0 = Bs[kk + fc][nt * 8 + fr];
                float b1 = Bs[kk + fc + 4][nt * 8 + fr];
                mma_tf32(acc[nt], a0, a1, a2, a3, b0, b1);
            }
        }
        __syncthreads();
    }

    int r0 = m0 + mw + fr;
    int r1 = r0 + 8;
#pragma unroll
    for (int nt = 0; nt < 8; nt++) {
        int cc = n0 + nt * 8 + fc * 2;
        float v00 = acc[nt][0], v01 = acc[nt][1];
        float v10 = acc[nt][2], v11 = acc[nt][3];
        if (HASBIAS) {
            float b0 = bias[cc], b1 = bias[cc + 1];
            v00 += b0; v01 += b1; v10 += b0; v11 += b1;
        }
        if (HASADD) {
            float2 a0 = *(const float2*)&addsrc[(size_t)r0 * Nd + cc];
            float2 a1 = *(const float2*)&addsrc[(size_t)r1 * Nd + cc];
            v00 += a0.x; v01 += a0.y; v10 += a1.x; v11 += a1.y;
        }
        if (RELU) {
            v00 = fmaxf(v00, 0.0f); v01 = fmaxf(v01, 0.0f);
            v10 = fmaxf(v10, 0.0f); v11 = fmaxf(v11, 0.0f);
        }
        if (OUTBF16) {
            __nv_bfloat162 h0 = __floats2bfloat162_rn(v00, v01);
            __nv_bfloat162 h1 = __floats2bfloat162_rn(v10, v11);
            *(uint32_t*)&g_qkvh[(size_t)r0 * Nd + cc] = *(uint32_t*)&h0;
            *(uint32_t*)&g_qkvh[(size_t)r1 * Nd + cc] = *(uint32_t*)&h1;
        } else {
            *(float2*)&C[(size_t)r0 * Nd + cc] = make_float2(v00, v01);
            *(float2*)&C[(size_t)r1 * Nd + cc] = make_float2(v10, v11);
        }
    }
}

// ---------------- bf16 tensor-core flash attention ----------------
__device__ __forceinline__ void mma_bf16(float c[4], uint32_t a0, uint32_t a1,
                                         uint32_t a2, uint32_t a3,
                                         uint32_t b0, uint32_t b1) {
    asm volatile(
        "mma.sync.aligned.m16n8k16.row.col.f32.bf16.bf16.f32 "
        "{%0,%1,%2,%3},{%4,%5,%6,%7},{%8,%9},{%0,%1,%2,%3};\n"
        : "+f"(c[0]), "+f"(c[1]), "+f"(c[2]), "+f"(c[3])
        : "r"(a0), "r"(a1), "r"(a2), "r"(a3), "r"(b0), "r"(b1));
}

#define FA_PITCH 72

__global__ __launch_bounds__(128) void flash_attn_bf16_kernel() {
    const __nv_bfloat16* __restrict__ qkvh = g_qkvh;
    float* __restrict__ outp = g_scratch + OFF_ATTN;
    const int head = blockIdx.y;
    const int q0 = blockIdx.x * 64;
    const int tid = threadIdx.x;
    const int warp = tid >> 5;
    const int lane = tid & 31;
    const int quad = lane >> 2;
    const int qd = lane & 3;

    __shared__ __align__(16) __nv_bfloat16 Qs[64][FA_PITCH];
    __shared__ __align__(16) __nv_bfloat16 Ks[64][FA_PITCH];
    __shared__ __align__(16) __nv_bfloat16 Vt[64][FA_PITCH];
    __shared__ __align__(16) __nv_bfloat16 Ps[64][FA_PITCH];

#pragma unroll
    for (int ch = 0; ch < 4; ch++) {
        int idx = ch * 128 + tid;
        int r = idx >> 3;
        int c = (idx & 7) * 8;
        *(uint4*)&Qs[r][c] =
            *(const uint4*)&qkvh[(size_t)(q0 + r) * 768 + head * 64 + c];
    }

    float m0r = -1e30f, m1r = -1e30f;
    float l0r = 0.0f, l1r = 0.0f;
    float o[8][4];
#pragma unroll
    for (int nt = 0; nt < 8; nt++)
#pragma unroll
        for (int j = 0; j < 4; j++) o[nt][j] = 0.0f;

    const int qrowA = warp * 16 + quad;
    const int qrowB = qrowA + 8;

    for (int kb = 0; kb < NN / 64; kb++) {
        int kbase = kb * 64;
        __syncthreads();
#pragma unroll
        for (int ch = 0; ch < 4; ch++) {
            int idx = ch * 128 + tid;
            int r = idx >> 3;
            int c = (idx & 7) * 8;
            *(uint4*)&Ks[r][c] =
                *(const uint4*)&qkvh[(size_t)(kbase + r) * 768 + 256 + head * 64 + c];
        }
        {
            int r = tid & 63;
            int d0 = (tid >> 6) * 32;
#pragma unroll
            for (int u = 0; u < 4; u++) {
                uint4 vv = *(const uint4*)&qkvh[(size_t)(kbase + r) * 768 + 512 +
                                                head * 64 + d0 + u * 8];
                __nv_bfloat16 tmp[8];
                *(uint4*)tmp = vv;
#pragma unroll
                for (int j = 0; j < 8; j++) Vt[d0 + u * 8 + j][r] = tmp[j];
            }
        }
        __syncthreads();

        float sc[8][4];
#pragma unroll
        for (int nt = 0; nt < 8; nt++)
#pragma unroll
            for (int j = 0; j < 4; j++) sc[nt][j] = 0.0f;

#pragma unroll
        for (int ks = 0; ks < 4; ks++) {
            int k0 = ks * 16;
            uint32_t a0 = *(const uint32_t*)&Qs[qrowA][k0 + qd * 2];
            uint32_t a1 = *(const uint32_t*)&Qs[qrowB][k0 + qd * 2];
            uint32_t a2 = *(const uint32_t*)&Qs[qrowA][k0 + qd * 2 + 8];
            uint32_t a3 = *(const uint32_t*)&Qs[qrowB][k0 + qd * 2 + 8];
#pragma unroll
            for (int nt = 0; nt < 8; nt++) {
                uint32_t b0 = *(const uint32_t*)&Ks[nt * 8 + quad][k0 + qd * 2];
                uint32_t b1 = *(const uint32_t*)&Ks[nt * 8 + quad][k0 + qd * 2 + 8];
                mma_bf16(sc[nt], a0, a1, a2, a3, b0, b1);
            }
        }

        float mA = -1e30f, mB = -1e30f;
#pragma unroll
        for (int nt = 0; nt < 8; nt++) {
            sc[nt][0] *= 0.125f; sc[nt][1] *= 0.125f;
            sc[nt][2] *= 0.125f; sc[nt][3] *= 0.125f;
            mA = fmaxf(mA, fmaxf(sc[nt][0], sc[nt][1]));
            mB = fmaxf(mB, fmaxf(sc[nt][2], sc[nt][3]));
        }
        mA = fmaxf(mA, __shfl_xor_sync(0xffffffffu, mA, 1));
        mA = fmaxf(mA, __shfl_xor_sync(0xffffffffu, mA, 2));
        mB = fmaxf(mB, __shfl_xor_sync(0xffffffffu, mB, 1));
        mB = fmaxf(mB, __shfl_xor_sync(0xffffffffu, mB, 2));
        float mnA = fmaxf(m0r, mA);
        float mnB = fmaxf(m1r, mB);
        float alA = __expf(m0r - mnA);
        float alB = __expf(m1r - mnB);
        float sumA = 0.0f, sumB = 0.0f;
#pragma unroll
        for (int nt = 0; nt < 8; nt++) {
            float p0 = __expf(sc[nt][0] - mnA);
            float p1 = __expf(sc[nt][1] - mnA);
            float p2 = __expf(sc[nt][2] - mnB);
            float p3 = __expf(sc[nt][3] - mnB);
            sumA += p0 + p1;
            sumB += p2 + p3;
            __nv_bfloat162 hA = __floats2bfloat162_rn(p0, p1);
            __nv_bfloat162 hB = __floats2bfloat162_rn(p2, p3);
            *(uint32_t*)&Ps[qrowA][nt * 8 + qd * 2] = *(uint32_t*)&hA;
            *(uint32_t*)&Ps[qrowB][nt * 8 + qd * 2] = *(uint32_t*)&hB;
        }
        sumA += __shfl_xor_sync(0xffffffffu, sumA, 1);
        sumA += __shfl_xor_sync(0xffffffffu, sumA, 2);
        sumB += __shfl_xor_sync(0xffffffffu, sumB, 1);
        sumB += __shfl_xor_sync(0xffffffffu, sumB, 2);
        l0r = l0r * alA + sumA;
        l1r = l1r * alB + sumB;
        m0r = mnA;
        m1r = mnB;
#pragma unroll
        for (int nt = 0; nt < 8; nt++) {
            o[nt][0] *= alA; o[nt][1] *= alA;
            o[nt][2] *= alB; o[nt][3] *= alB;
        }
        __syncwarp();

#pragma unroll
        for (int ks = 0; ks < 4; ks++) {
            int k0 = ks * 16;
            uint32_t a0 = *(const uint32_t*)&Ps[qrowA][k0 + qd * 2];
            uint32_t a1 = *(const uint32_t*)&Ps[qrowB][k0 + qd * 2];
            uint32_t a2 = *(const uint32_t*)&Ps[qrowA][k0 + qd * 2 + 8];
            uint32_t a3 = *(const uint32_t*)&Ps[qrowB][k0 + qd * 2 + 8];
#pragma unroll
            for (int nt = 0; nt < 8; nt++) {
                uint32_t b0 = *(const uint32_t*)&Vt[nt * 8 + quad][k0 + qd * 2];
                uint32_t b1 = *(const uint32_t*)&Vt[nt * 8 + quad][k0 + qd * 2 + 8];
                mma_bf16(o[nt], a0, a1, a2, a3, b0, b1);
            }
        }
    }

    float invA = 1.0f / l0r;
    float invB = 1.0f / l1r;
    int gA = q0 + qrowA;
    int gB = q0 + qrowB;
#pragma unroll
    for (int nt = 0; nt < 8; nt++) {
        float2 vA = make_float2(o[nt][0] * invA, o[nt][1] * invA);
        float2 vB = make_float2(o[nt][2] * invB, o[nt][3] * invB);
        *(float2*)&outp[(size_t)gA * IN_DIM + head * 64 + nt * 8 + qd * 2] = vA;
        *(float2*)&outp[(size_t)gB * IN_DIM + head * 64 + nt * 8 + qd * 2] = vB;
    }
}

// ---------------- launch ----------------
extern "C" void kernel_launch(void* const* d_in, const int* in_sizes, int n_in,
                              void* d_out, int out_size) {
    const float* x          = (const float*)d_in[0];
    const int*   ei         = (const int*)d_in[1];
    const float* gcn1_w     = (const float*)d_in[2];
    const float* gcn1_b     = (const float*)d_in[3];
    const float* gcn2_w     = (const float*)d_in[4];
    const float* gcn2_b     = (const float*)d_in[5];
    const float* lin_w      = (const float*)d_in[6];
    const float* lin_b      = (const float*)d_in[7];
    const float* in_proj_w  = (const float*)d_in[8];
    const float* in_proj_b  = (const float*)d_in[9];
    const float* out_proj_w = (const float*)d_in[10];
    const float* out_proj_b = (const float*)d_in[11];
    const float* proj_w     = (const float*)d_in[12];
    const float* proj_b     = (const float*)d_in[13];
    float* out = (float*)d_out;

    // CSR build + dinv
    zero_cnt_kernel<<<NN / 256, 256>>>();
    hist_kernel<<<EE / 256, 256>>>(ei);
    scan_kernel<<<1, 1024>>>();
    fill_kernel<<<EE / 256, 256>>>(ei);

    // ---- GNN branch ----
    gemm_tc<false, false, false, false, false><<<dim3(HIDDEN / 64, NN / 128), 256>>>(
        x, 0L, gcn1_w, nullptr, 0L, nullptr, OFF_H1, NN, IN_DIM, HIDDEN);
    gather_kernel<<<dim3(NN / 8, HIDDEN / 128), 256>>>(OFF_H1, gcn1_b, OFF_AGG1, HIDDEN);

    gemm_tc<false, false, false, false, false><<<dim3(HIDDEN / 64, NN / 128), 256>>>(
        nullptr, OFF_AGG1, gcn2_w, nullptr, 0L, nullptr, OFF_H2, NN, HIDDEN, HIDDEN);
    gather_kernel<<<dim3(NN / 8, HIDDEN / 128), 256>>>(OFF_H2, gcn2_b, OFF_AGG2, HIDDEN);

    gemm_tc<false, false, true, false, false><<<dim3(CLASSES / 64, NN / 128), 256>>>(
        nullptr, OFF_AGG2, lin_w, lin_b, 0L, nullptr, OFF_GNN, NN, HIDDEN, CLASSES);

    // ---- Transformer branch ----
    gemm_tc<true, false, true, false, true><<<dim3((3 * IN_DIM) / 64, NN / 128), 256>>>(
        x, 0L, in_proj_w, in_proj_b, 0L, nullptr, 0L, NN, IN_DIM, 3 * IN_DIM);

    flash_attn_bf16_kernel<<<dim3(NN / 64, HEADS), 128>>>();

    gemm_tc<true, false, true, false, false><<<dim3(IN_DIM / 64, NN / 128), 256>>>(
        nullptr, OFF_ATTN, out_proj_w, out_proj_b, 0L, nullptr, OFF_XTF, NN, IN_DIM, IN_DIM);

    gemm_tc<false, true, true, true, false><<<dim3(CLASSES / 64, NN / 128), 256>>>(
        nullptr, OFF_XTF, proj_w, proj_b, OFF_GNN, out, 0L, NN, IN_DIM, CLASSES);
}

// round 8
// speedup vs baseline: 2.7600x; 1.0194x over previous
#include <cuda_runtime.h>
#include <cuda_bf16.h>
#include <math.h>
#include <stdint.h>

#define NN 4096
#define IN_DIM 256
#define HIDDEN 512
#define CLASSES 256
#define HEADS 4
#define HD 64
#define EE 131072

// ---------------- scratch ----------------
#define OFF_DINV 0L
#define OFF_H1   (OFF_DINV + NN)
#define OFF_AGG1 (OFF_H1   + (long)NN * HIDDEN)
#define OFF_H2   (OFF_AGG1 + (long)NN * HIDDEN)
#define OFF_AGG2 (OFF_H2   + (long)NN * HIDDEN)
#define OFF_GNN  (OFF_AGG2 + (long)NN * HIDDEN)
#define OFF_ATTN (OFF_GNN  + (long)NN * CLASSES)
#define OFF_XTF  (OFF_ATTN + (long)NN * IN_DIM)
#define SCRATCH_TOTAL (OFF_XTF + (long)NN * IN_DIM)

__device__ __align__(16) float g_scratch[SCRATCH_TOTAL];
__device__ __align__(16) __nv_bfloat16 g_qkvh[(long)NN * 3 * IN_DIM];
__device__ int g_cnt[NN];
__device__ int g_rowptr[NN + 1];
__device__ int g_srcidx[EE];

// ---------------- CSR build ----------------
__global__ void zero_cnt_kernel() {
    int i = blockIdx.x * blockDim.x + threadIdx.x;
    if (i < NN) g_cnt[i] = 0;
}
__global__ void hist_kernel(const int* __restrict__ ei) {
    int i = blockIdx.x * blockDim.x + threadIdx.x;
    if (i < EE) atomicAdd(&g_cnt[ei[EE + i]], 1);
}
__global__ __launch_bounds__(1024) void scan_kernel() {
    __shared__ int sh[1024];
    int t = threadIdx.x;
    int base = t * 4;
    int c0 = g_cnt[base + 0], c1 = g_cnt[base + 1];
    int c2 = g_cnt[base + 2], c3 = g_cnt[base + 3];
    int s = c0 + c1 + c2 + c3;
    sh[t] = s;
    __syncthreads();
    for (int off = 1; off < 1024; off <<= 1) {
        int v = (t >= off) ? sh[t - off] : 0;
        __syncthreads();
        sh[t] += v;
        __syncthreads();
    }
    int run = sh[t] - s;
    g_rowptr[base + 0] = run;            run += c0;
    g_rowptr[base + 1] = run;            run += c1;
    g_rowptr[base + 2] = run;            run += c2;
    g_rowptr[base + 3] = run;            run += c3;
    if (t == 1023) g_rowptr[NN] = run;
    g_scratch[OFF_DINV + base + 0] = rsqrtf((float)c0 + 1.0f);
    g_scratch[OFF_DINV + base + 1] = rsqrtf((float)c1 + 1.0f);
    g_scratch[OFF_DINV + base + 2] = rsqrtf((float)c2 + 1.0f);
    g_scratch[OFF_DINV + base + 3] = rsqrtf((float)c3 + 1.0f);
    g_cnt[base + 0] = 0; g_cnt[base + 1] = 0;
    g_cnt[base + 2] = 0; g_cnt[base + 3] = 0;
}
__global__ void fill_kernel(const int* __restrict__ ei) {
    int e = blockIdx.x * blockDim.x + threadIdx.x;
    if (e >= EE) return;
    int dst = ei[EE + e];
    int pos = g_rowptr[dst] + atomicAdd(&g_cnt[dst], 1);
    g_srcidx[pos] = ei[e];
}

// ---------------- fused GCN aggregation (gather) ----------------
__global__ __launch_bounds__(256) void gather_kernel(long hoff, const float* __restrict__ bias,
                                                     long aggoff, int F) {
    const float* __restrict__ h = g_scratch + hoff;
    float* __restrict__ agg = g_scratch + aggoff;
    const float* __restrict__ dinv = g_scratch + OFF_DINV;
    const int warp = threadIdx.x >> 5;
    const int lane = threadIdx.x & 31;
    const int node = blockIdx.x * 8 + warp;
    const int c = blockIdx.y * 128 + lane * 4;

    float dd = dinv[node];
    float4 b4 = *(const float4*)&bias[c];
    float4 hv = *(const float4*)&h[(size_t)node * F + c];
    float sw = dd * dd;
    float4 acc = make_float4(hv.x * sw + b4.x, hv.y * sw + b4.y,
                             hv.z * sw + b4.z, hv.w * sw + b4.w);

    int beg = g_rowptr[node];
    int end = g_rowptr[node + 1];
    for (int j = beg; j < end; j++) {
        int src = g_srcidx[j];
        float w = dinv[src] * dd;
        float4 v = *(const float4*)&h[(size_t)src * F + c];
        acc.x += v.x * w; acc.y += v.y * w;
        acc.z += v.z * w; acc.w += v.w * w;
    }
    acc.x = fmaxf(acc.x, 0.0f); acc.y = fmaxf(acc.y, 0.0f);
    acc.z = fmaxf(acc.z, 0.0f); acc.w = fmaxf(acc.w, 0.0f);
    *(float4*)&agg[(size_t)node * F + c] = acc;
}

// ---------------- tf32 helpers ----------------
__device__ __forceinline__ float to_tf32(float x) {
    float r;
    asm("cvt.rna.tf32.f32 %0, %1;" : "=f"(r) : "f"(x));
    return r;
}
__device__ __forceinline__ void mma_tf32(float c[4], float a0, float a1, float a2,
                                         float a3, float b0, float b1) {
    uint32_t ua0 = __float_as_uint(a0), ua1 = __float_as_uint(a1);
    uint32_t ua2 = __float_as_uint(a2), ua3 = __float_as_uint(a3);
    uint32_t ub0 = __float_as_uint(b0), ub1 = __float_as_uint(b1);
    asm volatile(
        "mma.sync.aligned.m16n8k8.row.col.f32.tf32.tf32.f32 "
        "{%0,%1,%2,%3},{%4,%5,%6,%7},{%8,%9},{%0,%1,%2,%3};\n"
        : "+f"(c[0]), "+f"(c[1]), "+f"(c[2]), "+f"(c[3])
        : "r"(ua0), "r"(ua1), "r"(ua2), "r"(ua3), "r"(ub0), "r"(ub1));
}

// ---------------- tf32 tensor-core GEMM, double buffered ----------------
// BM=128, BN=64, BK=16, 256 threads (8 warps)
#define AP 20
#define BPN 72  // non-trans B: Bs[k][n], pad 72
#define BPT 20  // trans B:    Bs[n][k], pad 20
template <bool TRANSB, bool RELU, bool HASBIAS, bool HASADD, bool OUTBF16>
__global__ __launch_bounds__(256) void gemm_tc(const float* __restrict__ Aext, long aoff,
                                               const float* __restrict__ B,
                                               const float* __restrict__ bias,
                                               long addoff,
                                               float* __restrict__ Cext, long coff,
                                               int M, int K, int Nd) {
    const float* __restrict__ A = Aext ? Aext : (const float*)(g_scratch + aoff);
    float* __restrict__ C = Cext ? Cext : (g_scratch + coff);
    const float* __restrict__ addsrc = g_scratch + (HASADD ? addoff : 0);

    constexpr int BSZ = TRANSB ? 64 * BPT : 16 * BPN;
    __shared__ float As[2][128][AP];
    __shared__ float Bs[2][BSZ];

    const int tid = threadIdx.x;
    const int warp = tid >> 5, lane = tid & 31;
    const int fr = lane >> 2, fc = lane & 3;
    const int mw = warp * 16;
    const int m0 = blockIdx.y * 128, n0 = blockIdx.x * 64;

    // staging indices
    const int am0 = tid >> 2;                // A rows for u=0 (0..63)? no: idx=u*256+tid
    const int akq = (tid & 3) * 4;
    const int bn = tid >> 2;                 // trans: n row 0..63
    const int bkq = (tid & 3) * 4;           // trans: k col
    const int bkr = tid >> 4;                // nontrans: k row 0..15
    const int bn4 = (tid & 15) * 4;          // nontrans: n col

    float4 pa0, pa1, pb;

    // prologue: load tile 0
    {
        int m_a0 = (0 * 256 + tid) >> 2, m_a1 = (1 * 256 + tid) >> 2;
        pa0 = *(const float4*)(A + (size_t)(m0 + m_a0) * K + akq);
        pa1 = *(const float4*)(A + (size_t)(m0 + m_a1) * K + akq);
        if (TRANSB)
            pb = *(const float4*)(B + (size_t)(n0 + bn) * K + bkq);
        else
            pb = *(const float4*)(B + (size_t)bkr * Nd + n0 + bn4);
    }

    float acc[8][4];
#pragma unroll
    for (int nt = 0; nt < 8; nt++)
#pragma unroll
        for (int j = 0; j < 4; j++) acc[nt][j] = 0.0f;

    const int nk = K >> 4;

    // store tile 0
    {
        int m_a0 = tid >> 2, m_a1 = 64 + (tid >> 2);
        As[0][m_a0][akq + 0] = to_tf32(pa0.x);
        As[0][m_a0][akq + 1] = to_tf32(pa0.y);
        As[0][m_a0][akq + 2] = to_tf32(pa0.z);
        As[0][m_a0][akq + 3] = to_tf32(pa0.w);
        As[0][m_a1][akq + 0] = to_tf32(pa1.x);
        As[0][m_a1][akq + 1] = to_tf32(pa1.y);
        As[0][m_a1][akq + 2] = to_tf32(pa1.z);
        As[0][m_a1][akq + 3] = to_tf32(pa1.w);
        if (TRANSB) {
            float* bp = &Bs[0][bn * BPT + bkq];
            bp[0] = to_tf32(pb.x); bp[1] = to_tf32(pb.y);
            bp[2] = to_tf32(pb.z); bp[3] = to_tf32(pb.w);
        } else {
            float* bp = &Bs[0][bkr * BPN + bn4];
            bp[0] = to_tf32(pb.x); bp[1] = to_tf32(pb.y);
            bp[2] = to_tf32(pb.z); bp[3] = to_tf32(pb.w);
        }
    }
    __syncthreads();

    for (int k0i = 0; k0i < nk; k0i++) {
        const int cur = k0i & 1, nxt = cur ^ 1;
        const bool more = (k0i + 1) < nk;
        // issue next tile gmem loads
        if (more) {
            int k0 = (k0i + 1) << 4;
            int m_a0 = tid >> 2, m_a1 = 64 + (tid >> 2);
            pa0 = *(const float4*)(A + (size_t)(m0 + m_a0) * K + k0 + akq);
            pa1 = *(const float4*)(A + (size_t)(m0 + m_a1) * K + k0 + akq);
            if (TRANSB)
                pb = *(const float4*)(B + (size_t)(n0 + bn) * K + k0 + bkq);
            else
                pb = *(const float4*)(B + (size_t)(k0 + bkr) * Nd + n0 + bn4);
        }

        // compute on cur
#pragma unroll
        for (int ks = 0; ks < 2; ks++) {
            int kk = ks * 8;
            float a0 = As[cur][mw + fr][kk + fc];
            float a1 = As[cur][mw + fr + 8][kk + fc];
            float a2 = As[cur][mw + fr][kk + fc + 4];
            float a3 = As[cur][mw + fr + 8][kk + fc + 4];
#pragma unroll
            for (int nt = 0; nt < 8; nt++) {
                float b0, b1;
                if (TRANSB) {
                    b0 = Bs[cur][(nt * 8 + fr) * BPT + kk + fc];
                    b1 = Bs[cur][(nt * 8 + fr) * BPT + kk + fc + 4];
                } else {
                    b0 = Bs[cur][(kk + fc) * BPN + nt * 8 + fr];
                    b1 = Bs[cur][(kk + fc + 4) * BPN + nt * 8 + fr];
                }
                mma_tf32(acc[nt], a0, a1, a2, a3, b0, b1);
            }
        }

        // store next tile
        if (more) {
            int m_a0 = tid >> 2, m_a1 = 64 + (tid >> 2);
            As[nxt][m_a0][akq + 0] = to_tf32(pa0.x);
            As[nxt][m_a0][akq + 1] = to_tf32(pa0.y);
            As[nxt][m_a0][akq + 2] = to_tf32(pa0.z);
            As[nxt][m_a0][akq + 3] = to_tf32(pa0.w);
            As[nxt][m_a1][akq + 0] = to_tf32(pa1.x);
            As[nxt][m_a1][akq + 1] = to_tf32(pa1.y);
            As[nxt][m_a1][akq + 2] = to_tf32(pa1.z);
            As[nxt][m_a1][akq + 3] = to_tf32(pa1.w);
            if (TRANSB) {
                float* bp = &Bs[nxt][bn * BPT + bkq];
                bp[0] = to_tf32(pb.x); bp[1] = to_tf32(pb.y);
                bp[2] = to_tf32(pb.z); bp[3] = to_tf32(pb.w);
            } else {
                float* bp = &Bs[nxt][bkr * BPN + bn4];
                bp[0] = to_tf32(pb.x); bp[1] = to_tf32(pb.y);
                bp[2] = to_tf32(pb.z); bp[3] = to_tf32(pb.w);
            }
            __syncthreads();
        }
    }

    // epilogue
    int r0 = m0 + mw + fr;
    int r1 = r0 + 8;
#pragma unroll
    for (int nt = 0; nt < 8; nt++) {
        int cc = n0 + nt * 8 + fc * 2;
        float v00 = acc[nt][0], v01 = acc[nt][1];
        float v10 = acc[nt][2], v11 = acc[nt][3];
        if (HASBIAS) {
            float b0 = bias[cc], b1 = bias[cc + 1];
            v00 += b0; v01 += b1; v10 += b0; v11 += b1;
        }
        if (HASADD) {
            float2 a0 = *(const float2*)&addsrc[(size_t)r0 * Nd + cc];
            float2 a1 = *(const float2*)&addsrc[(size_t)r1 * Nd + cc];
            v00 += a0.x; v01 += a0.y; v10 += a1.x; v11 += a1.y;
        }
        if (RELU) {
            v00 = fmaxf(v00, 0.0f); v01 = fmaxf(v01, 0.0f);
            v10 = fmaxf(v10, 0.0f); v11 = fmaxf(v11, 0.0f);
        }
        if (OUTBF16) {
            __nv_bfloat162 h0 = __floats2bfloat162_rn(v00, v01);
            __nv_bfloat162 h1 = __floats2bfloat162_rn(v10, v11);
            *(uint32_t*)&g_qkvh[(size_t)r0 * Nd + cc] = *(uint32_t*)&h0;
            *(uint32_t*)&g_qkvh[(size_t)r1 * Nd + cc] = *(uint32_t*)&h1;
        } else {
            *(float2*)&C[(size_t)r0 * Nd + cc] = make_float2(v00, v01);
            *(float2*)&C[(size_t)r1 * Nd + cc] = make_float2(v10, v11);
        }
    }
}

// ---------------- bf16 tensor-core flash attention ----------------
__device__ __forceinline__ void mma_bf16(float c[4], uint32_t a0, uint32_t a1,
                                         uint32_t a2, uint32_t a3,
                                         uint32_t b0, uint32_t b1) {
    asm volatile(
        "mma.sync.aligned.m16n8k16.row.col.f32.bf16.bf16.f32 "
        "{%0,%1,%2,%3},{%4,%5,%6,%7},{%8,%9},{%0,%1,%2,%3};\n"
        : "+f"(c[0]), "+f"(c[1]), "+f"(c[2]), "+f"(c[3])
        : "r"(a0), "r"(a1), "r"(a2), "r"(a3), "r"(b0), "r"(b1));
}

#define FA_PITCH 72

__global__ __launch_bounds__(128) void flash_attn_bf16_kernel() {
    const __nv_bfloat16* __restrict__ qkvh = g_qkvh;
    float* __restrict__ outp = g_scratch + OFF_ATTN;
    const int head = blockIdx.y;
    const int q0 = blockIdx.x * 64;
    const int tid = threadIdx.x;
    const int warp = tid >> 5;
    const int lane = tid & 31;
    const int quad = lane >> 2;
    const int qd = lane & 3;

    __shared__ __align__(16) __nv_bfloat16 Qs[64][FA_PITCH];
    __shared__ __align__(16) __nv_bfloat16 Ks[64][FA_PITCH];
    __shared__ __align__(16) __nv_bfloat16 Vt[64][FA_PITCH];
    __shared__ __align__(16) __nv_bfloat16 Ps[64][FA_PITCH];

#pragma unroll
    for (int ch = 0; ch < 4; ch++) {
        int idx = ch * 128 + tid;
        int r = idx >> 3;
        int c = (idx & 7) * 8;
        *(uint4*)&Qs[r][c] =
            *(const uint4*)&qkvh[(size_t)(q0 + r) * 768 + head * 64 + c];
    }

    float m0r = -1e30f, m1r = -1e30f;
    float l0r = 0.0f, l1r = 0.0f;
    float o[8][4];
#pragma unroll
    for (int nt = 0; nt < 8; nt++)
#pragma unroll
        for (int j = 0; j < 4; j++) o[nt][j] = 0.0f;

    const int qrowA = warp * 16 + quad;
    const int qrowB = qrowA + 8;

    for (int kb = 0; kb < NN / 64; kb++) {
        int kbase = kb * 64;
        __syncthreads();
#pragma unroll
        for (int ch = 0; ch < 4; ch++) {
            int idx = ch * 128 + tid;
            int r = idx >> 3;
            int c = (idx & 7) * 8;
            *(uint4*)&Ks[r][c] =
                *(const uint4*)&qkvh[(size_t)(kbase + r) * 768 + 256 + head * 64 + c];
        }
        {
            int r = tid & 63;
            int d0 = (tid >> 6) * 32;
#pragma unroll
            for (int u = 0; u < 4; u++) {
                uint4 vv = *(const uint4*)&qkvh[(size_t)(kbase + r) * 768 + 512 +
                                                head * 64 + d0 + u * 8];
                __nv_bfloat16 tmp[8];
                *(uint4*)tmp = vv;
#pragma unroll
                for (int j = 0; j < 8; j++) Vt[d0 + u * 8 + j][r] = tmp[j];
            }
        }
        __syncthreads();

        float sc[8][4];
#pragma unroll
        for (int nt = 0; nt < 8; nt++)
#pragma unroll
            for (int j = 0; j < 4; j++) sc[nt][j] = 0.0f;

#pragma unroll
        for (int ks = 0; ks < 4; ks++) {
            int k0 = ks * 16;
            uint32_t a0 = *(const uint32_t*)&Qs[qrowA][k0 + qd * 2];
            uint32_t a1 = *(const uint32_t*)&Qs[qrowB][k0 + qd * 2];
            uint32_t a2 = *(const uint32_t*)&Qs[qrowA][k0 + qd * 2 + 8];
            uint32_t a3 = *(const uint32_t*)&Qs[qrowB][k0 + qd * 2 + 8];
#pragma unroll
            for (int nt = 0; nt < 8; nt++) {
                uint32_t b0 = *(const uint32_t*)&Ks[nt * 8 + quad][k0 + qd * 2];
                uint32_t b1 = *(const uint32_t*)&Ks[nt * 8 + quad][k0 + qd * 2 + 8];
                mma_bf16(sc[nt], a0, a1, a2, a3, b0, b1);
            }
        }

        float mA = -1e30f, mB = -1e30f;
#pragma unroll
        for (int nt = 0; nt < 8; nt++) {
            sc[nt][0] *= 0.125f; sc[nt][1] *= 0.125f;
            sc[nt][2] *= 0.125f; sc[nt][3] *= 0.125f;
            mA = fmaxf(mA, fmaxf(sc[nt][0], sc[nt][1]));
            mB = fmaxf(mB, fmaxf(sc[nt][2], sc[nt][3]));
        }
        mA = fmaxf(mA, __shfl_xor_sync(0xffffffffu, mA, 1));
        mA = fmaxf(mA, __shfl_xor_sync(0xffffffffu, mA, 2));
        mB = fmaxf(mB, __shfl_xor_sync(0xffffffffu, mB, 1));
        mB = fmaxf(mB, __shfl_xor_sync(0xffffffffu, mB, 2));
        float mnA = fmaxf(m0r, mA);
        float mnB = fmaxf(m1r, mB);
        float alA = __expf(m0r - mnA);
        float alB = __expf(m1r - mnB);
        float sumA = 0.0f, sumB = 0.0f;
#pragma unroll
        for (int nt = 0; nt < 8; nt++) {
            float p0 = __expf(sc[nt][0] - mnA);
            float p1 = __expf(sc[nt][1] - mnA);
            float p2 = __expf(sc[nt][2] - mnB);
            float p3 = __expf(sc[nt][3] - mnB);
            sumA += p0 + p1;
            sumB += p2 + p3;
            __nv_bfloat162 hA = __floats2bfloat162_rn(p0, p1);
            __nv_bfloat162 hB = __floats2bfloat162_rn(p2, p3);
            *(uint32_t*)&Ps[qrowA][nt * 8 + qd * 2] = *(uint32_t*)&hA;
            *(uint32_t*)&Ps[qrowB][nt * 8 + qd * 2] = *(uint32_t*)&hB;
        }
        sumA += __shfl_xor_sync(0xffffffffu, sumA, 1);
        sumA += __shfl_xor_sync(0xffffffffu, sumA, 2);
        sumB += __shfl_xor_sync(0xffffffffu, sumB, 1);
        sumB += __shfl_xor_sync(0xffffffffu, sumB, 2);
        l0r = l0r * alA + sumA;
        l1r = l1r * alB + sumB;
        m0r = mnA;
        m1r = mnB;
#pragma unroll
        for (int nt = 0; nt < 8; nt++) {
            o[nt][0] *= alA; o[nt][1] *= alA;
            o[nt][2] *= alB; o[nt][3] *= alB;
        }
        __syncwarp();

#pragma unroll
        for (int ks = 0; ks < 4; ks++) {
            int k0 = ks * 16;
            uint32_t a0 = *(const uint32_t*)&Ps[qrowA][k0 + qd * 2];
            uint32_t a1 = *(const uint32_t*)&Ps[qrowB][k0 + qd * 2];
            uint32_t a2 = *(const uint32_t*)&Ps[qrowA][k0 + qd * 2 + 8];
            uint32_t a3 = *(const uint32_t*)&Ps[qrowB][k0 + qd * 2 + 8];
#pragma unroll
            for (int nt = 0; nt < 8; nt++) {
                uint32_t b0 = *(const uint32_t*)&Vt[nt * 8 + quad][k0 + qd * 2];
                uint32_t b1 = *(const uint32_t*)&Vt[nt * 8 + quad][k0 + qd * 2 + 8];
                mma_bf16(o[nt], a0, a1, a2, a3, b0, b1);
            }
        }
    }

    float invA = 1.0f / l0r;
    float invB = 1.0f / l1r;
    int gA = q0 + qrowA;
    int gB = q0 + qrowB;
#pragma unroll
    for (int nt = 0; nt < 8; nt++) {
        float2 vA = make_float2(o[nt][0] * invA, o[nt][1] * invA);
        float2 vB = make_float2(o[nt][2] * invB, o[nt][3] * invB);
        *(float2*)&outp[(size_t)gA * IN_DIM + head * 64 + nt * 8 + qd * 2] = vA;
        *(float2*)&outp[(size_t)gB * IN_DIM + head * 64 + nt * 8 + qd * 2] = vB;
    }
}

// ---------------- launch ----------------
extern "C" void kernel_launch(void* const* d_in, const int* in_sizes, int n_in,
                              void* d_out, int out_size) {
    const float* x          = (const float*)d_in[0];
    const int*   ei         = (const int*)d_in[1];
    const float* gcn1_w     = (const float*)d_in[2];
    const float* gcn1_b     = (const float*)d_in[3];
    const float* gcn2_w     = (const float*)d_in[4];
    const float* gcn2_b     = (const float*)d_in[5];
    const float* lin_w      = (const float*)d_in[6];
    const float* lin_b      = (const float*)d_in[7];
    const float* in_proj_w  = (const float*)d_in[8];
    const float* in_proj_b  = (const float*)d_in[9];
    const float* out_proj_w = (const float*)d_in[10];
    const float* out_proj_b = (const float*)d_in[11];
    const float* proj_w     = (const float*)d_in[12];
    const float* proj_b     = (const float*)d_in[13];
    float* out = (float*)d_out;

    // CSR build + dinv
    zero_cnt_kernel<<<NN / 256, 256>>>();
    hist_kernel<<<EE / 256, 256>>>(ei);
    scan_kernel<<<1, 1024>>>();
    fill_kernel<<<EE / 256, 256>>>(ei);

    // ---- GNN branch ----
    gemm_tc<false, false, false, false, false><<<dim3(HIDDEN / 64, NN / 128), 256>>>(
        x, 0L, gcn1_w, nullptr, 0L, nullptr, OFF_H1, NN, IN_DIM, HIDDEN);
    gather_kernel<<<dim3(NN / 8, HIDDEN / 128), 256>>>(OFF_H1, gcn1_b, OFF_AGG1, HIDDEN);

    gemm_tc<false, false, false, false, false><<<dim3(HIDDEN / 64, NN / 128), 256>>>(
        nullptr, OFF_AGG1, gcn2_w, nullptr, 0L, nullptr, OFF_H2, NN, HIDDEN, HIDDEN);
    gather_kernel<<<dim3(NN / 8, HIDDEN / 128), 256>>>(OFF_H2, gcn2_b, OFF_AGG2, HIDDEN);

    gemm_tc<false, false, true, false, false><<<dim3(CLASSES / 64, NN / 128), 256>>>(
        nullptr, OFF_AGG2, lin_w, lin_b, 0L, nullptr, OFF_GNN, NN, HIDDEN, CLASSES);

    // ---- Transformer branch ----
    gemm_tc<true, false, true, false, true><<<dim3((3 * IN_DIM) / 64, NN / 128), 256>>>(
        x, 0L, in_proj_w, in_proj_b, 0L, nullptr, 0L, NN, IN_DIM, 3 * IN_DIM);

    flash_attn_bf16_kernel<<<dim3(NN / 64, HEADS), 128>>>();

    gemm_tc<true, false, true, false, false><<<dim3(IN_DIM / 64, NN / 128), 256>>>(
        nullptr, OFF_ATTN, out_proj_w, out_proj_b, 0L, nullptr, OFF_XTF, NN, IN_DIM, IN_DIM);

    gemm_tc<false, true, true, true, false><<<dim3(CLASSES / 64, NN / 128), 256>>>(
        nullptr, OFF_XTF, proj_w, proj_b, OFF_GNN, out, 0L, NN, IN_DIM, CLASSES);
}